// round 12
// baseline (speedup 1.0000x reference)
#include <cuda_runtime.h>

// out[b, l, i, j] = emission[b, l, j] + transition[i, j]
// B=32, L=512, T=64. Output = 256 MB fp32 — pure write-stream bound at the
// full-chip LTS cap (ncu plateau 40.6-41.9us; wall band 43.5-43.8us).
//
// A/B EXPERIMENT (single variable): default-policy v8 stores instead of .cs
// evict-first. The .cs hint was introduced together with v8+unroll in R2 and
// never isolated. Tests whether default L2 eviction drains writebacks in
// larger row-coherent spans than evict-first's early small bursts.
// Everything else identical to the R10 final config.
//
// One warp per (b,l) row (16384 warps). Lane: j8 = lane&7, igrp = lane>>3.
// Emission chunk register-resident (loaded once, reused 16x); 16 iterations
// over transition rows (L1-resident), each storing 1KB contiguous per warp.

__device__ __forceinline__ void ldg256(const float* p, float4& a, float4& b) {
    asm volatile("ld.global.nc.v8.f32 {%0,%1,%2,%3,%4,%5,%6,%7}, [%8];"
                 : "=f"(a.x), "=f"(a.y), "=f"(a.z), "=f"(a.w),
                   "=f"(b.x), "=f"(b.y), "=f"(b.z), "=f"(b.w)
                 : "l"(p));
}

__device__ __forceinline__ void stg256(float* p, float4 a, float4 b) {
    asm volatile("st.global.v8.f32 [%0], {%1,%2,%3,%4,%5,%6,%7,%8};"
                 :: "l"(p),
                    "f"(a.x), "f"(a.y), "f"(a.z), "f"(a.w),
                    "f"(b.x), "f"(b.y), "f"(b.z), "f"(b.w)
                 : "memory");
}

__global__ __launch_bounds__(128)
void CRF_53128745451552_kernel(const float* __restrict__ em,
                               const float* __restrict__ tr,
                               float* __restrict__ out) {
    int warp = (blockIdx.x * blockDim.x + threadIdx.x) >> 5;  // = bl, 0..16383
    int lane = threadIdx.x & 31;
    int j8   = lane & 7;    // 8-float chunk within j (0..7)
    int igrp = lane >> 3;   // i offset within a 4-row group (0..3)

    // Emission chunk for this (bl, j8): loaded once, reused 16x.
    float4 e0, e1;
    ldg256(em + ((size_t)warp << 6) + (j8 << 3), e0, e1);

    const float* tp = tr  + (igrp << 6) + (j8 << 3);
    float*       op = out + ((size_t)warp << 12) + (igrp << 6) + (j8 << 3);

#pragma unroll 4
    for (int it = 0; it < 16; it++) {
        float4 t0, t1;
        ldg256(tp + it * 256, t0, t1);   // transition[it*4+igrp, j8*8..] (L1 hit)

        float4 r0, r1;
        r0.x = e0.x + t0.x;  r0.y = e0.y + t0.y;
        r0.z = e0.z + t0.z;  r0.w = e0.w + t0.w;
        r1.x = e1.x + t1.x;  r1.y = e1.y + t1.y;
        r1.z = e1.z + t1.z;  r1.w = e1.w + t1.w;

        stg256(op + it * 256, r0, r1);  // warp-iter: 1KB contiguous
    }
}

extern "C" void kernel_launch(void* const* d_in, const int* in_sizes, int n_in,
                              void* d_out, int out_size) {
    const float* em = (const float*)d_in[0];   // emission [32, 512, 64] fp32
    const float* tr = (const float*)d_in[1];   // transition [64, 64] fp32
    float* out = (float*)d_out;

    // 16384 rows, one warp each; 128 threads = 4 warps per block -> 4096 blocks.
    CRF_53128745451552_kernel<<<4096, 128>>>(em, tr, out);
}

// round 13
// speedup vs baseline: 1.0066x; 1.0066x over previous
#include <cuda_runtime.h>

// out[b, l, i, j] = emission[b, l, j] + transition[i, j]
// B=32, L=512, T=64. Output = 256 MB fp32 — pure write-stream bound.
//
// FINAL KERNEL. ncu 40.6us / wall 43.5-43.8us, at the full-chip LTS/HBM
// write ceiling (L1/L2/DRAM all co-pinned ~2/3; store policy A/B identical;
// TMA store documented path-equivalent). Explored & rejected: deeper reuse
// (reg pressure), persistent grid (tail imbalance), block-quantum sweep
// (noise), .cs vs default stores (identical).
//
// One warp per (b,l) row (16384 warps). Lane: j8 = lane&7, igrp = lane>>3.
// Emission chunk register-resident (loaded once, reused 16x); 16 iterations
// over transition rows (L1-resident after warmup), each iteration storing
// 1KB contiguous per warp via v8 (256-bit) evict-first stores.

__device__ __forceinline__ void ldg256(const float* p, float4& a, float4& b) {
    asm volatile("ld.global.nc.v8.f32 {%0,%1,%2,%3,%4,%5,%6,%7}, [%8];"
                 : "=f"(a.x), "=f"(a.y), "=f"(a.z), "=f"(a.w),
                   "=f"(b.x), "=f"(b.y), "=f"(b.z), "=f"(b.w)
                 : "l"(p));
}

__device__ __forceinline__ void stg256_cs(float* p, float4 a, float4 b) {
    asm volatile("st.global.cs.v8.f32 [%0], {%1,%2,%3,%4,%5,%6,%7,%8};"
                 :: "l"(p),
                    "f"(a.x), "f"(a.y), "f"(a.z), "f"(a.w),
                    "f"(b.x), "f"(b.y), "f"(b.z), "f"(b.w)
                 : "memory");
}

__global__ __launch_bounds__(128)
void CRF_53128745451552_kernel(const float* __restrict__ em,
                               const float* __restrict__ tr,
                               float* __restrict__ out) {
    int warp = (blockIdx.x * blockDim.x + threadIdx.x) >> 5;  // = bl, 0..16383
    int lane = threadIdx.x & 31;
    int j8   = lane & 7;    // 8-float chunk within j (0..7)
    int igrp = lane >> 3;   // i offset within a 4-row group (0..3)

    // Emission chunk for this (bl, j8): loaded once, reused 16x.
    float4 e0, e1;
    ldg256(em + ((size_t)warp << 6) + (j8 << 3), e0, e1);

    const float* tp = tr  + (igrp << 6) + (j8 << 3);
    float*       op = out + ((size_t)warp << 12) + (igrp << 6) + (j8 << 3);

#pragma unroll 4
    for (int it = 0; it < 16; it++) {
        float4 t0, t1;
        ldg256(tp + it * 256, t0, t1);   // transition[it*4+igrp, j8*8..] (L1 hit)

        float4 r0, r1;
        r0.x = e0.x + t0.x;  r0.y = e0.y + t0.y;
        r0.z = e0.z + t0.z;  r0.w = e0.w + t0.w;
        r1.x = e1.x + t1.x;  r1.y = e1.y + t1.y;
        r1.z = e1.z + t1.z;  r1.w = e1.w + t1.w;

        stg256_cs(op + it * 256, r0, r1);  // warp-iter: 1KB contiguous
    }
}

extern "C" void kernel_launch(void* const* d_in, const int* in_sizes, int n_in,
                              void* d_out, int out_size) {
    const float* em = (const float*)d_in[0];   // emission [32, 512, 64] fp32
    const float* tr = (const float*)d_in[1];   // transition [64, 64] fp32
    float* out = (float*)d_out;

    // 16384 rows, one warp each; 128 threads = 4 warps per block -> 4096 blocks.
    CRF_53128745451552_kernel<<<4096, 128>>>(em, tr, out);
}